// round 1
// baseline (speedup 1.0000x reference)
#include <cuda_runtime.h>

// RNN forward, fused persistent kernel.
// B=256, T=1024, IN=4, H=256, OUT=1.
// 128 CTAs x 256 threads; CTA handles 2 batches for all 1024 steps.
// Wh register-resident (176/256 values per thread) + 80KB streamed from smem.
// Inner product uses fma.rn.f32x2 (FFMA2) for 128 MAC/cyc/SM.

typedef unsigned long long u64;

#define T_LEN   1024
#define HID     256
#define KG_LEN  64          // k per k-group (4 groups across 8 warps, 2 h-groups)

__device__ __forceinline__ u64 ffma2(u64 a, u64 b, u64 c) {
    u64 d;
    asm("fma.rn.f32x2 %0, %1, %2, %3;" : "=l"(d) : "l"(a), "l"(b), "l"(c));
    return d;
}
__device__ __forceinline__ float lo32(u64 v) { return __uint_as_float((unsigned)(v & 0xffffffffu)); }
__device__ __forceinline__ float hi32(u64 v) { return __uint_as_float((unsigned)(v >> 32)); }

// shared memory byte offsets
#define SM_WHS   0                  // ulonglong2 WHS[8][20][32]   = 81920 B
#define SM_HBUF  81920              // float hbuf[2][2][256]       = 4096 B
#define SM_PART  86016              // float part[4][2][256]       = 8192 B
#define SM_XS    94208              // float xs[2][8]              = 64 B
#define SM_TOTAL 94272

__global__ void __launch_bounds__(256, 1)
rnn_kernel(const float* __restrict__ x,        // [256][1024][4]
           const float* __restrict__ W_i2h,    // [256][260]  (cols 0..3 = Wx, 4..259 = Wh)
           const float* __restrict__ b_i2h,    // [256]
           const float* __restrict__ W_h2o,    // [256]
           const float* __restrict__ b_h2o,    // [1]
           const float* __restrict__ init_h,   // [256]
           float* __restrict__ out)            // [256]
{
    extern __shared__ unsigned char sm[];
    ulonglong2* WHS = (ulonglong2*)(sm + SM_WHS);
    float* hbuf = (float*)(sm + SM_HBUF);
    float* part = (float*)(sm + SM_PART);
    float* xs   = (float*)(sm + SM_XS);

    const int t  = threadIdx.x;
    const int w  = t >> 5;
    const int l  = t & 31;
    const int kg = w & 3;             // k-group: k in [64*kg, 64*kg+64)
    const int hg = w >> 2;            // h-group: h in [128*hg, 128*hg+128)
    const int kbase = kg * KG_LEN;

    const int b0 = blockIdx.x * 2;

    // the 4 hidden rows this thread computes partials for
    const int h0r = hg * 128 + l;           // + i*32 for i in 0..3

    // ---- load Wh: rows 0,1 + first 24 pairs of row 2 into registers (88 pairs = 176 regs);
    //      rest of row 2 + all of row 3 into smem (20 ulonglong2 per thread = 80KB/CTA) ----
    u64 wreg[88];
    {
        #pragma unroll
        for (int i = 0; i < 2; i++) {
            const ulonglong2* rp = (const ulonglong2*)(W_i2h + (size_t)(h0r + i*32) * 260 + 4 + kbase);
            #pragma unroll
            for (int jj = 0; jj < 16; jj++) {
                ulonglong2 v = rp[jj];
                wreg[i*32 + 2*jj]     = v.x;
                wreg[i*32 + 2*jj + 1] = v.y;
            }
        }
        const ulonglong2* rp2 = (const ulonglong2*)(W_i2h + (size_t)(h0r + 2*32) * 260 + 4 + kbase);
        #pragma unroll
        for (int jj = 0; jj < 12; jj++) {
            ulonglong2 v = rp2[jj];
            wreg[64 + 2*jj]     = v.x;
            wreg[64 + 2*jj + 1] = v.y;
        }
        #pragma unroll
        for (int jj = 12; jj < 16; jj++)
            WHS[(w*20 + (jj - 12))*32 + l] = rp2[jj];
        const ulonglong2* rp3 = (const ulonglong2*)(W_i2h + (size_t)(h0r + 3*32) * 260 + 4 + kbase);
        #pragma unroll
        for (int jj = 0; jj < 16; jj++)
            WHS[(w*20 + 4 + jj)*32 + l] = rp3[jj];
    }

    // reducer-role parameters for h = t
    const float4 wx = *(const float4*)(W_i2h + (size_t)t * 260);   // Wx[t][0..3]
    const float bi = b_i2h[t];
    const float wo = W_h2o[t];
    const float bo = b_h2o[0];

    // init hidden state (buffer 0) and x for step 0
    {
        float hv = init_h[t];
        hbuf[0*512 + 0*256 + t] = hv;
        hbuf[0*512 + 1*256 + t] = hv;
        if (t < 2) {
            float4 xv = *(const float4*)(x + ((size_t)(b0 + t) * T_LEN + 0) * 4);
            *(float4*)(xs + t*4) = xv;
        }
    }
    __syncthreads();

    float pool0 = 0.0f, pool1 = 0.0f;
    int cur = 0;

    for (int step = 0; step < T_LEN; step++) {
        const int nxt = cur ^ 1;

        // prefetch x for next step (threads 0,1)
        float4 xv;
        if (t < 2) {
            int tn = (step < T_LEN - 1) ? (step + 1) : step;
            xv = *(const float4*)(x + ((size_t)(b0 + t) * T_LEN + tn) * 4);
        }

        // xproj for h = t (this thread's reducer role)
        const float* xsc = xs + cur*8;
        float xp0 = bi + wx.x*xsc[0] + wx.y*xsc[1] + wx.z*xsc[2] + wx.w*xsc[3];
        float xp1 = bi + wx.x*xsc[4] + wx.y*xsc[5] + wx.z*xsc[6] + wx.w*xsc[7];

        // partial dot products over this warp's k range
        const ulonglong2* hp0 = (const ulonglong2*)(hbuf + cur*512 + 0*256 + kbase);
        const ulonglong2* hp1 = (const ulonglong2*)(hbuf + cur*512 + 1*256 + kbase);

        u64 acc[4][2];
        #pragma unroll
        for (int i = 0; i < 4; i++) { acc[i][0] = 0ULL; acc[i][1] = 0ULL; }

        #pragma unroll
        for (int jj = 0; jj < 16; jj++) {
            ulonglong2 h0v = hp0[jj];     // h[b0], k pairs (2jj, 2jj+1)
            ulonglong2 h1v = hp1[jj];     // h[b1]
            #pragma unroll
            for (int i = 0; i < 2; i++) {
                u64 wa = wreg[i*32 + 2*jj];
                u64 wb = wreg[i*32 + 2*jj + 1];
                acc[i][0] = ffma2(wa, h0v.x, acc[i][0]);
                acc[i][0] = ffma2(wb, h0v.y, acc[i][0]);
                acc[i][1] = ffma2(wa, h1v.x, acc[i][1]);
                acc[i][1] = ffma2(wb, h1v.y, acc[i][1]);
            }
            u64 wa2, wb2;
            if (jj < 12) { wa2 = wreg[64 + 2*jj]; wb2 = wreg[64 + 2*jj + 1]; }
            else { ulonglong2 v = WHS[(w*20 + (jj - 12))*32 + l]; wa2 = v.x; wb2 = v.y; }
            acc[2][0] = ffma2(wa2, h0v.x, acc[2][0]);
            acc[2][0] = ffma2(wb2, h0v.y, acc[2][0]);
            acc[2][1] = ffma2(wa2, h1v.x, acc[2][1]);
            acc[2][1] = ffma2(wb2, h1v.y, acc[2][1]);
            ulonglong2 v3 = WHS[(w*20 + 4 + jj)*32 + l];
            acc[3][0] = ffma2(v3.x, h0v.x, acc[3][0]);
            acc[3][0] = ffma2(v3.y, h0v.y, acc[3][0]);
            acc[3][1] = ffma2(v3.x, h1v.x, acc[3][1]);
            acc[3][1] = ffma2(v3.y, h1v.y, acc[3][1]);
        }

        // write partial sums: part[kg][b][h]
        #pragma unroll
        for (int i = 0; i < 4; i++) {
            int hh = h0r + i*32;
            part[(kg*2 + 0)*256 + hh] = lo32(acc[i][0]) + hi32(acc[i][0]);
            part[(kg*2 + 1)*256 + hh] = lo32(acc[i][1]) + hi32(acc[i][1]);
        }
        __syncthreads();

        // reduce across the 4 k-groups for h = t, tanh, pool, store new state
        float pre0 = xp0 + ((part[0*256 + t] + part[2*256 + t]) +
                            (part[4*256 + t] + part[6*256 + t]));
        float pre1 = xp1 + ((part[1*256 + t] + part[3*256 + t]) +
                            (part[5*256 + t] + part[7*256 + t]));
        float hn0 = tanhf(pre0);
        float hn1 = tanhf(pre1);
        pool0 += hn0;
        pool1 += hn1;
        hbuf[nxt*512 + 0*256 + t] = hn0;
        hbuf[nxt*512 + 1*256 + t] = hn1;
        if (t < 2) *(float4*)(xs + nxt*8 + t*4) = xv;
        __syncthreads();
        cur = nxt;
    }

    // output head: out[b] = mean_t(h)[b] . W_h2o + b_h2o
    float v0 = pool0 * (1.0f / 1024.0f) * wo;
    float v1 = pool1 * (1.0f / 1024.0f) * wo;
    #pragma unroll
    for (int o = 16; o > 0; o >>= 1) {
        v0 += __shfl_down_sync(0xffffffffu, v0, o);
        v1 += __shfl_down_sync(0xffffffffu, v1, o);
    }
    if (l == 0) { part[w] = v0; part[8 + w] = v1; }
    __syncthreads();
    if (t == 0) {
        float s = 0.0f;
        #pragma unroll
        for (int i = 0; i < 8; i++) s += part[i];
        out[b0] = s + bo;
    } else if (t == 1) {
        float s = 0.0f;
        #pragma unroll
        for (int i = 0; i < 8; i++) s += part[8 + i];
        out[b0 + 1] = s + bo;
    }
}

extern "C" void kernel_launch(void* const* d_in, const int* in_sizes, int n_in,
                              void* d_out, int out_size) {
    const float* x     = (const float*)d_in[0];
    const float* W_i2h = (const float*)d_in[1];
    const float* b_i2h = (const float*)d_in[2];
    const float* W_h2o = (const float*)d_in[3];
    const float* b_h2o = (const float*)d_in[4];
    const float* ih    = (const float*)d_in[5];
    float* outp = (float*)d_out;

    cudaFuncSetAttribute(rnn_kernel, cudaFuncAttributeMaxDynamicSharedMemorySize, SM_TOTAL);
    rnn_kernel<<<128, 256, SM_TOTAL>>>(x, W_i2h, b_i2h, W_h2o, b_h2o, ih, outp);
}